// round 8
// baseline (speedup 1.0000x reference)
#include <cuda_runtime.h>
#include <math.h>

#define BB 16
#define CC 256
#define TT 4096
#define KK 5

#define WIN  166   // per-channel window: x[t0-16 .. t0+149]
#define WOFF 16

// Packed duplicated rp1 weights: g_wt2[(c*3 + d)*128 + c2] = (w,w) as f32x2.
__device__ unsigned long long g_wt2[CC * 3 * 128];

__global__ void transpose_rp1(const float* __restrict__ rp1_w) {
    int idx = blockIdx.x * blockDim.x + threadIdx.x;
    if (idx >= CC * 3 * 128) return;
    int c2 = idx & 127;
    int cd = idx >> 7;
    int d = cd % 3;
    int c = cd / 3;
    float w = rp1_w[(c2 * CC + c) * 3 + d];
    unsigned long long p;
    asm("mov.b64 %0, {%1, %2};" : "=l"(p) : "f"(w), "f"(w));
    g_wt2[idx] = p;
}

#define FFMA2(acc, a, b) asm("fma.rn.f32x2 %0, %1, %2, %0;" : "+l"(acc) : "l"(a), "l"(b))

__device__ __forceinline__ void unpackf2(unsigned long long v, float& lo, float& hi) {
    asm("mov.b64 {%0, %1}, %2;" : "=f"(lo), "=f"(hi) : "l"(v));
}

// ---------------------------------------------------------------------------
// Kernel 1 (v3): offset/modulator convs + sigmoid + deformable sampling +
// diag einsum -> deformed[b][c][t].
// ALL 256 channel windows persist in smem: staged ONCE, used by both the
// offset conv (Phase A) and the gather (Phase B). No mid-kernel re-staging.
// Numerics (values + fma order) bit-identical to rounds 5-7 (knife-edge).
// Dynamic smem: s_w 7680 | s_dw 1280 | s_win 256*166 = 51456 floats (201 KB).
// ---------------------------------------------------------------------------
#define DEF_SMEM_FLOATS (CC * 30 + CC * KK + CC * WIN)

__global__ __launch_bounds__(128) void k_deform(
    const float* __restrict__ x,
    const float* __restrict__ ow, const float* __restrict__ ob,
    const float* __restrict__ mw, const float* __restrict__ mb,
    const float* __restrict__ weight,
    float* __restrict__ deformed)
{
    extern __shared__ float dsm_d[];
    float* s_w   = dsm_d;                      // [c][k*3+d] offset | mod
    float* s_dw  = dsm_d + CC * 30;            // diag weights [c][k]
    float* s_win = dsm_d + CC * 30 + CC * KK;  // windows [c][WIN]

    const int tid = threadIdx.x;
    const int t0 = blockIdx.x * 128;
    const int b = blockIdx.y;
    const float* xb = x + (size_t)b * CC * TT;

    // conv weights -> smem
    for (int i = tid; i < CC * 30; i += 128) {
        int c = i / 30;
        int j = i - c * 30;
        float v;
        if (j < 15) {
            int k = j / 3, d = j - k * 3;
            v = ow[k * (CC * 3) + c * 3 + d];
        } else {
            int jj = j - 15;
            int k = jj / 3, d = jj - k * 3;
            v = mw[k * (CC * 3) + c * 3 + d];
        }
        s_w[i] = v;
    }
    // diag weights -> smem
    for (int i = tid; i < CC * KK; i += 128) {
        int c = i / KK;
        int k = i - c * KK;
        s_dw[i] = __ldg(weight + ((size_t)c * CC + c) * KK + k);
    }
    // ALL channel windows -> smem (once). Interior blocks take the unguarded
    // vectorized path (WIN=166 floats: 41 float4 + 2 scalars per channel).
    if (t0 >= WOFF && t0 + 149 < TT) {
        const float4* xb4 = reinterpret_cast<const float4*>(xb + (t0 - WOFF));
        for (int idx = tid; idx < CC * 42; idx += 128) {
            int ci = idx / 42;
            int q = idx - ci * 42;
            const float4* src = xb4 + ci * (TT / 4);
            float* dst = s_win + ci * WIN;
            if (q < 41) {
                float4 v = __ldg(src + q);
                dst[q * 4 + 0] = v.x;
                dst[q * 4 + 1] = v.y;
                dst[q * 4 + 2] = v.z;
                dst[q * 4 + 3] = v.w;
            } else {
                const float* s = xb + (size_t)ci * TT + (t0 - WOFF);
                dst[164] = __ldg(s + 164);
                dst[165] = __ldg(s + 165);
            }
        }
    } else {
        for (int idx = tid; idx < CC * WIN; idx += 128) {
            int ci = idx / WIN;
            int u = idx - ci * WIN;
            int tg = t0 - WOFF + u;
            s_win[ci * WIN + u] = (tg >= 0 && tg < TT) ? __ldg(xb + (size_t)ci * TT + tg) : 0.f;
        }
    }
    __syncthreads();

    // Phase A: 10-channel conv (chunk-folded fp32 accumulation — frozen order)
    float offa[KK] = {0.f, 0.f, 0.f, 0.f, 0.f};
    float moda[KK] = {0.f, 0.f, 0.f, 0.f, 0.f};
    for (int cc = 0; cc < CC; cc += 32) {
        float offc[KK] = {0.f, 0.f, 0.f, 0.f, 0.f};
        float modc[KK] = {0.f, 0.f, 0.f, 0.f, 0.f};
        #pragma unroll 1
        for (int ci = 0; ci < 32; ci++) {
            const float* wrow = s_w + (cc + ci) * 30;
            const float* xs = s_win + (cc + ci) * WIN + tid + (WOFF - 1);
            float x0 = xs[0];
            float x1 = xs[1];
            float x2 = xs[2];
            #pragma unroll
            for (int k = 0; k < KK; k++) {
                offc[k] += x0 * wrow[k * 3 + 0] + x1 * wrow[k * 3 + 1] + x2 * wrow[k * 3 + 2];
                modc[k] += x0 * wrow[15 + k * 3 + 0] + x1 * wrow[15 + k * 3 + 1] + x2 * wrow[15 + k * 3 + 2];
            }
        }
        #pragma unroll
        for (int k = 0; k < KK; k++) { offa[k] += offc[k]; moda[k] += modc[k]; }
    }

    // positions / interp weights (exact fp32 — frozen)
    const int t = t0 + tid;
    float mf[KK], mc[KK];
    int pfi[KK], pci[KK];
    #pragma unroll
    for (int k = 0; k < KK; k++) {
        float off = offa[k] + __ldg(ob + k);
        float z = moda[k] + __ldg(mb + k);
        float mod = 1.f / (1.f + expf(-z));
        float pos = (float)(t + k - 2) + off;
        pos = fminf(fmaxf(pos, 0.f), (float)(TT - 1));
        float pf = floorf(pos);
        float pc = ceilf(pos);
        mf[k] = (pc - pos) * mod;
        mc[k] = (pos - pf) * mod;
        pfi[k] = (int)pf;
        pci[k] = (int)pc;
    }

    // window indices + warp vote
    int idxf[KK], idxc[KK];
    bool allin = true;
    #pragma unroll
    for (int k = 0; k < KK; k++) {
        idxf[k] = pfi[k] - (t0 - WOFF);
        idxc[k] = pci[k] - (t0 - WOFF);
        allin = allin && ((unsigned)idxf[k] < (unsigned)WIN) && ((unsigned)idxc[k] < (unsigned)WIN);
    }
    const bool fast = __all_sync(0xffffffffu, allin);

    // Phase B: sample + diag einsum from the SAME resident windows
    float* db = deformed + (size_t)b * CC * TT;
    if (fast) {
        #pragma unroll 2
        for (int c = 0; c < CC; c++) {
            const float* xs = s_win + c * WIN;
            const float* dwc = s_dw + c * KK;
            float acc = 0.f;
            #pragma unroll
            for (int k = 0; k < KK; k++) {
                float s = xs[idxf[k]] * mf[k] + xs[idxc[k]] * mc[k];
                acc = fmaf(s, dwc[k], acc);
            }
            db[(size_t)c * TT + t] = acc;
        }
    } else {
        #pragma unroll 1
        for (int c = 0; c < CC; c++) {
            const float* xc = xb + (size_t)c * TT;
            const float* dwc = s_dw + c * KK;
            float acc = 0.f;
            #pragma unroll
            for (int k = 0; k < KK; k++) {
                float s = __ldg(xc + pfi[k]) * mf[k] + __ldg(xc + pci[k]) * mc[k];
                acc = fmaf(s, dwc[k], acc);
            }
            db[(size_t)c * TT + t] = acc;
        }
    }
}

// ---------------------------------------------------------------------------
// Kernel 2: UNCHANGED (at its fp32 FMA-pipe ceiling; tensor-core rewrite is
// the next project). Dynamic smem 69632 B.
// ---------------------------------------------------------------------------
#define REC_SMEM_FLOATS (CC * 32 + CC * 36)

__global__ __launch_bounds__(128) void k_recover(
    const float* __restrict__ deformed,
    const float* __restrict__ rp1_b,
    const float* __restrict__ rp2_w,
    const float* __restrict__ rp2_b,
    float* __restrict__ recovery)
{
    extern __shared__ float dsm[];
    float* sA = dsm;
    float* sB = dsm + CC * 32;
    __shared__ float sp[4 * 33];

    const int tid = threadIdx.x;
    const int t0 = blockIdx.x * 32;
    const int b = blockIdx.y;
    const float* db = deformed + (size_t)b * CC * TT;

    for (int idx = tid; idx < CC * 34; idx += 128) {
        int c = idx / 34;
        int u = idx - c * 34;
        int tg = t0 + u - 1;
        float v = (tg >= 0 && tg < TT) ? db[(size_t)c * TT + tg] : 0.f;
        sB[c * 36 + u] = v;
        int vv = u - 1;
        if (vv >= 0 && vv < 32) sA[c * 32 + vv] = v;
    }
    __syncthreads();

    unsigned long long acc2[16];
    #pragma unroll
    for (int j = 0; j < 16; j++) acc2[j] = 0ull;

    const int c2 = tid;
    const unsigned long long* W = g_wt2 + c2;
    unsigned long long w0n = __ldg(W);
    unsigned long long w1n = __ldg(W + 128);
    unsigned long long w2n = __ldg(W + 256);

    #pragma unroll 1
    for (int c = 0; c < CC; c++) {
        unsigned long long w0p = w0n, w1p = w1n, w2p = w2n;
        if (c < CC - 1) {
            const unsigned long long* Wn = W + (c + 1) * 384;
            w0n = __ldg(Wn);
            w1n = __ldg(Wn + 128);
            w2n = __ldg(Wn + 256);
        }
        const ulonglong2* A128 = reinterpret_cast<const ulonglong2*>(sA + c * 32);
        const ulonglong2* B128 = reinterpret_cast<const ulonglong2*>(sB + c * 36);
        ulonglong2 bq = B128[0];
        #pragma unroll
        for (int q = 0; q < 8; q++) {
            ulonglong2 aq = A128[q];
            ulonglong2 bq1 = B128[q + 1];
            FFMA2(acc2[2 * q], bq.x, w0p);
            FFMA2(acc2[2 * q], aq.x, w1p);
            FFMA2(acc2[2 * q], bq.y, w2p);
            FFMA2(acc2[2 * q + 1], bq.y, w0p);
            FFMA2(acc2[2 * q + 1], aq.y, w1p);
            FFMA2(acc2[2 * q + 1], bq1.x, w2p);
            bq = bq1;
        }
    }

    const float b1 = __ldg(rp1_b + c2);
    const float w2c = __ldg(rp2_w + c2);

    __syncthreads();
    float* sc = dsm;
    #pragma unroll
    for (int j = 0; j < 16; j++) {
        float h0, h1;
        unpackf2(acc2[j], h0, h1);
        h0 = fmaxf(h0 + b1, 0.f) * w2c;
        h1 = fmaxf(h1 + b1, 0.f) * w2c;
        sc[(2 * j) * 129 + c2] = h0;
        sc[(2 * j + 1) * 129 + c2] = h1;
    }
    __syncthreads();

    {
        int tl = tid & 31;
        int w = tid >> 5;
        const float* row = sc + tl * 129 + w * 32;
        float s = 0.f;
        #pragma unroll
        for (int i = 0; i < 32; i++) s += row[i];
        sp[w * 33 + tl] = s;
    }
    __syncthreads();

    if (tid < 32) {
        float r = sp[tid] + sp[33 + tid] + sp[66 + tid] + sp[99 + tid] + __ldg(rp2_b);
        recovery[(size_t)b * TT + t0 + tid] = r;
    }
}

// ---------------------------------------------------------------------------
extern "C" void kernel_launch(void* const* d_in, const int* in_sizes, int n_in,
                              void* d_out, int out_size) {
    const float* x     = (const float*)d_in[0];
    const float* ow    = (const float*)d_in[1];
    const float* ob    = (const float*)d_in[2];
    const float* mw    = (const float*)d_in[3];
    const float* mb    = (const float*)d_in[4];
    const float* wgt   = (const float*)d_in[5];
    const float* rp1_w = (const float*)d_in[6];
    const float* rp1_b = (const float*)d_in[7];
    const float* rp2_w = (const float*)d_in[8];
    const float* rp2_b = (const float*)d_in[9];

    float* out = (float*)d_out;
    float* deformed = out;                              // (B, C, T)
    float* recovery = out + (size_t)BB * CC * TT;       // (B, T)

    cudaFuncSetAttribute(k_deform, cudaFuncAttributeMaxDynamicSharedMemorySize,
                         DEF_SMEM_FLOATS * (int)sizeof(float));
    cudaFuncSetAttribute(k_recover, cudaFuncAttributeMaxDynamicSharedMemorySize,
                         REC_SMEM_FLOATS * (int)sizeof(float));

    k_deform<<<dim3(TT / 128, BB), 128, DEF_SMEM_FLOATS * sizeof(float)>>>(
        x, ow, ob, mw, mb, wgt, deformed);
    transpose_rp1<<<(CC * 3 * 128 + 255) / 256, 256>>>(rp1_w);
    k_recover<<<dim3(TT / 32, BB), 128, REC_SMEM_FLOATS * sizeof(float)>>>(
        deformed, rp1_b, rp2_w, rp2_b, recovery);
}